// round 14
// baseline (speedup 1.0000x reference)
#include <cuda_runtime.h>
#include <cstdint>

// ---------------- problem constants ----------------
#define BB   2048      // batch
#define LL   64        // words / sentence
#define DD   300       // embedding dim (K of encoder GEMM)
#define CC   512       // conv out channels
#define HH   2048      // fc hidden
// encoder GEMM: M = BB*LL = 131072, N = CC = 512, K = 300
// fc1 GEMM:     M = BB = 2048,     N = HH = 2048, K = 2*CC = 1024

#define WCP  304       // padded K for the tf32 Wc image

// ---------------- scratch (no allocations allowed) ----------------
__device__ float    g_e[2 * BB * CC];            // e1 | e2   (8 MB)
__device__ float    g_h[(size_t)BB * HH];        // tanh hidden (16 MB)
__device__ uint32_t g_wtf[CC * WCP];             // tf32 image of Wc (0.6 MB)
__device__ uint32_t g_w1tf[(size_t)HH * 2 * CC]; // tf32 image of W1 (8 MB)

// ---------------- helpers ----------------
__device__ __forceinline__ uint32_t f2tf(float f) {
    uint32_t r;
    asm("cvt.rna.tf32.f32 %0, %1;" : "=r"(r) : "f"(f));
    return r;
}

__device__ __forceinline__ void mma_tf32(float c[4], const uint32_t a[4], const uint32_t b[2]) {
    asm volatile(
        "mma.sync.aligned.m16n8k8.row.col.f32.tf32.tf32.f32 "
        "{%0,%1,%2,%3}, {%4,%5,%6,%7}, {%8,%9}, {%0,%1,%2,%3};"
        : "+f"(c[0]), "+f"(c[1]), "+f"(c[2]), "+f"(c[3])
        : "r"(a[0]), "r"(a[1]), "r"(a[2]), "r"(a[3]), "r"(b[0]), "r"(b[1]));
}

__device__ __forceinline__ void cpa16(uint32_t dst, const void* src, int sz) {
    asm volatile("cp.async.cg.shared.global [%0], [%1], 16, %2;"
                 :: "r"(dst), "l"(src), "r"(sz));
}
__device__ __forceinline__ void cpa_commit() {
    asm volatile("cp.async.commit_group;");
}

// ---------------- tiling ----------------
// CTA tile: 256 (M) x 128 (N), K-tile 32, 8 warps each owning a 64x64 subtile.
#define KT    32
#define PADW  36                       // smem row stride (words)
#define AW    (256 * PADW)             // words per A stage
#define BWW   (128 * PADW)             // words per B stage
#define SMEM_WORDS (2 * (AW + BWW))
#define SMEM_BYTES (SMEM_WORDS * 4)    // 110592

// ---------------- per-warp compute on one staged K-tile (raw tf32 smem) ----
template <int NKS>
__device__ __forceinline__ void compute_tile(const uint32_t* __restrict__ As,
                                             const uint32_t* __restrict__ Bs,
                                             int wm, int wn, int g, int tg,
                                             float acc[4][8][4])
{
    #pragma unroll
    for (int kk = 0; kk < NKS * 8; kk += 8) {
        uint32_t a[4][4], b[8][2];
        #pragma unroll
        for (int f = 0; f < 4; f++) {
            int r = wm * 64 + f * 16;
            a[f][0] = As[(r + g    ) * PADW + kk + tg    ];
            a[f][1] = As[(r + g + 8) * PADW + kk + tg    ];
            a[f][2] = As[(r + g    ) * PADW + kk + tg + 4];
            a[f][3] = As[(r + g + 8) * PADW + kk + tg + 4];
        }
        #pragma unroll
        for (int ni = 0; ni < 8; ni++) {
            int c = wn * 64 + ni * 8;
            b[ni][0] = Bs[(c + g) * PADW + kk + tg    ];
            b[ni][1] = Bs[(c + g) * PADW + kk + tg + 4];
        }
        #pragma unroll
        for (int f = 0; f < 4; f++)
            #pragma unroll
            for (int ni = 0; ni < 8; ni++)
                mma_tf32(acc[f][ni], a[f], b[ni]);
    }
}

// =====================================================================
// Kernel 0a/0b: one-time tf32 images of the weights
// =====================================================================
__global__ __launch_bounds__(256)
void cvt_wc_kernel(const float* __restrict__ Wc)
{
    int idx = blockIdx.x * 256 + threadIdx.x;
    if (idx >= CC * WCP) return;
    int row = idx / WCP, col = idx % WCP;
    g_wtf[idx] = (col < DD) ? f2tf(Wc[(size_t)row * DD + col]) : 0u;
}

__global__ __launch_bounds__(256)
void cvt_w1_kernel(const float* __restrict__ W1)
{
    size_t idx = (size_t)blockIdx.x * 256 + threadIdx.x;
    // HH * 2C = 4194304 elements -> 1048576 float4 chunks
    const float4* s = (const float4*)W1;
    float4 v = s[idx];
    uint4 t = make_uint4(f2tf(v.x), f2tf(v.y), f2tf(v.z), f2tf(v.w));
    *(uint4*)(g_w1tf + idx * 4) = t;
}

// =====================================================================
// Kernel 1: encoder.  grid = (C/128, (B*L)/256, 2), block = 256
// relu(max_L(x @ Wc^T) + bc) folded into epilogue; warp m-strip = 1 sentence.
// A: LDG x -> regs -> cvt@STS (double-buffered).  B: cp.async raw of g_wtf.
// =====================================================================
__global__ __launch_bounds__(256, 1)
void encode_kernel(const float* __restrict__ x1, const float* __restrict__ x2,
                   const float* __restrict__ bc)
{
    extern __shared__ uint32_t sh[];
    uint32_t sbase = (uint32_t)__cvta_generic_to_shared(sh);

    const float* __restrict__ x = (blockIdx.z == 0) ? x1 : x2;
    const int mbase = blockIdx.y * 256;
    const int nbase = blockIdx.x * 128;

    const int tid  = threadIdx.x;
    const int warp = tid >> 5, lane = tid & 31;
    const int wm = warp >> 1;      // 4 m-strips of 64 rows (one sentence each)
    const int wn = warp & 1;       // 2 n-strips of 64 cols
    const int g  = lane >> 2, tg = lane & 3;

    const int lrow = tid >> 3;     // loader row base
    const int kch  = (tid & 7) * 4;

    float4 ra[8];

    auto ldgA = [&](int kb) {
        const int k = kb + kch;
        #pragma unroll
        for (int it = 0; it < 8; it++) {
            int row = lrow + it * 32;
            ra[it] = (k < DD)
                ? *(const float4*)(x + (size_t)(mbase + row) * DD + k)
                : make_float4(0.f, 0.f, 0.f, 0.f);
        }
    };
    auto stsA = [&](int buf) {
        #pragma unroll
        for (int it = 0; it < 8; it++) {
            int row = lrow + it * 32;
            uint32_t* d = sh + buf * AW + row * PADW + kch;
            d[0] = f2tf(ra[it].x); d[1] = f2tf(ra[it].y);
            d[2] = f2tf(ra[it].z); d[3] = f2tf(ra[it].w);
        }
    };
    auto cpB = [&](int buf, int kb) {
        const int k = kb + kch;
        #pragma unroll
        for (int it = 0; it < 4; it++) {
            int row = lrow + it * 32;
            const uint32_t* src = g_wtf + (size_t)(nbase + row) * WCP + k;
            uint32_t dst = sbase + (uint32_t)(2 * AW + buf * BWW + row * PADW + kch) * 4u;
            cpa16(dst, src, (k < WCP) ? 16 : 0);
        }
    };

    float acc[4][8][4] = {};

    const int NK = 10;     // K tiles of 32 (300 -> 320 padded; last tile trimmed)
    // prologue
    cpB(0, 0);
    cpa_commit();
    ldgA(0);
    stsA(0);
    asm volatile("cp.async.wait_group 0;");
    __syncthreads();

    #pragma unroll 1
    for (int i = 0; i < NK; i++) {
        if (i + 1 < NK) {
            cpB((i + 1) & 1, (i + 1) * KT);
            cpa_commit();
            ldgA((i + 1) * KT);
        }

        const uint32_t* As = sh + (i & 1) * AW;
        const uint32_t* Bs = sh + 2 * AW + (i & 1) * BWW;
        if (i == NK - 1)   // k = 288..303 covers the 300 real columns
            compute_tile<2>(As, Bs, wm, wn, g, tg, acc);
        else
            compute_tile<4>(As, Bs, wm, wn, g, tg, acc);

        if (i + 1 < NK) {
            stsA((i + 1) & 1);
            asm volatile("cp.async.wait_group 0;");
            __syncthreads();
        }
    }

    // ---- epilogue: max over the warp's 64 rows (== one sentence) ----
    // relu(max + bc) == max(relu(.+bc)) since bias is per-column.
    const size_t sent = (size_t)blockIdx.y * 4 + wm;       // global sentence
    float* __restrict__ eout = g_e + ((size_t)blockIdx.z * BB + sent) * CC + nbase;

    #pragma unroll
    for (int ni = 0; ni < 8; ni++) {
        #pragma unroll
        for (int j = 0; j < 2; j++) {
            float m = -3.4e38f;
            #pragma unroll
            for (int f = 0; f < 4; f++)
                m = fmaxf(m, fmaxf(acc[f][ni][j], acc[f][ni][j + 2]));
            #pragma unroll
            for (int off = 4; off < 32; off <<= 1)
                m = fmaxf(m, __shfl_xor_sync(0xffffffffu, m, off));
            if (g == 0) {
                int col = wn * 64 + ni * 8 + 2 * tg + j;
                eout[col] = fmaxf(m + bc[nbase + col], 0.f);
            }
        }
    }
}

// =====================================================================
// Kernel 2: FC1.  grid = (H/128, B/256), block = 256
// feat = [e1-e2 | e1*e2] computed on the fly (A-side, cvt at STS).
// B: cp.async raw of g_w1tf.  h = tanh(feat @ W1^T + b1)
// =====================================================================
__global__ __launch_bounds__(256, 1)
void fc1_kernel(const float* __restrict__ b1)
{
    extern __shared__ uint32_t sh[];
    uint32_t sbase = (uint32_t)__cvta_generic_to_shared(sh);

    const int mbase = blockIdx.y * 256;
    const int nbase = blockIdx.x * 128;

    const int tid  = threadIdx.x;
    const int warp = tid >> 5, lane = tid & 31;
    const int wm = warp >> 1, wn = warp & 1;
    const int g  = lane >> 2, tg = lane & 3;

    const float* __restrict__ e1 = g_e;
    const float* __restrict__ e2 = g_e + (size_t)BB * CC;

    const int lrow = tid >> 3;
    const int kch  = (tid & 7) * 4;

    float acc[4][8][4] = {};
    float4 ra[8];

    auto ldgA = [&](int kb) {
        const int j = kb + kch;
        #pragma unroll
        for (int it = 0; it < 8; it++) {
            int r = mbase + lrow + it * 32;
            if (j < CC) {
                float4 p = *(const float4*)(e1 + (size_t)r * CC + j);
                float4 q = *(const float4*)(e2 + (size_t)r * CC + j);
                ra[it] = make_float4(p.x - q.x, p.y - q.y, p.z - q.z, p.w - q.w);
            } else {
                int j2 = j - CC;
                float4 p = *(const float4*)(e1 + (size_t)r * CC + j2);
                float4 q = *(const float4*)(e2 + (size_t)r * CC + j2);
                ra[it] = make_float4(p.x * q.x, p.y * q.y, p.z * q.z, p.w * q.w);
            }
        }
    };
    auto stsA = [&](int buf) {
        #pragma unroll
        for (int it = 0; it < 8; it++) {
            int row = lrow + it * 32;
            uint32_t* d = sh + buf * AW + row * PADW + kch;
            d[0] = f2tf(ra[it].x); d[1] = f2tf(ra[it].y);
            d[2] = f2tf(ra[it].z); d[3] = f2tf(ra[it].w);
        }
    };
    auto cpB = [&](int buf, int kb) {
        const int j = kb + kch;
        #pragma unroll
        for (int it = 0; it < 4; it++) {
            int row = lrow + it * 32;
            const uint32_t* src = g_w1tf + (size_t)(nbase + row) * (2 * CC) + j;
            uint32_t dst = sbase + (uint32_t)(2 * AW + buf * BWW + row * PADW + kch) * 4u;
            cpa16(dst, src, 16);
        }
    };

    const int NK = (2 * CC) / KT;   // 32
    // prologue
    cpB(0, 0);
    cpa_commit();
    ldgA(0);
    stsA(0);
    asm volatile("cp.async.wait_group 0;");
    __syncthreads();

    #pragma unroll 1
    for (int i = 0; i < NK; i++) {
        if (i + 1 < NK) {
            cpB((i + 1) & 1, (i + 1) * KT);
            cpa_commit();
            ldgA((i + 1) * KT);
        }

        const uint32_t* As = sh + (i & 1) * AW;
        const uint32_t* Bs = sh + 2 * AW + (i & 1) * BWW;
        compute_tile<4>(As, Bs, wm, wn, g, tg, acc);

        if (i + 1 < NK) {
            stsA((i + 1) & 1);
            asm volatile("cp.async.wait_group 0;");
            __syncthreads();
        }
    }

    // epilogue: bias + tanh, direct store
    #pragma unroll
    for (int f = 0; f < 4; f++) {
        #pragma unroll
        for (int ni = 0; ni < 8; ni++) {
            #pragma unroll
            for (int q = 0; q < 4; q++) {
                int row = mbase + wm * 64 + f * 16 + g + ((q >> 1) ? 8 : 0);
                int col = nbase + wn * 64 + ni * 8 + 2 * tg + (q & 1);
                g_h[(size_t)row * HH + col] = tanhf(acc[f][ni][q] + b1[col]);
            }
        }
    }
}

// =====================================================================
// Kernel 3: FC2 (H -> 1), fp32, float4 loads.  grid = B, block = 256
// =====================================================================
__global__ __launch_bounds__(256)
void fc2_kernel(const float* __restrict__ W2, const float* __restrict__ b2,
                float* __restrict__ out)
{
    const int b = blockIdx.x;
    const float4* __restrict__ h4 = (const float4*)(g_h + (size_t)b * HH);
    const float4* __restrict__ w4 = (const float4*)W2;
    float s = 0.f;
    #pragma unroll
    for (int i = 0; i < 2; i++) {
        int idx = threadIdx.x + i * 256;
        float4 hv = h4[idx], wv = w4[idx];
        s += hv.x * wv.x + hv.y * wv.y + hv.z * wv.z + hv.w * wv.w;
    }
    #pragma unroll
    for (int off = 16; off > 0; off >>= 1)
        s += __shfl_xor_sync(0xffffffffu, s, off);
    __shared__ float sm[8];
    int warp = threadIdx.x >> 5, lane = threadIdx.x & 31;
    if (lane == 0) sm[warp] = s;
    __syncthreads();
    if (warp == 0) {
        float v = (lane < 8) ? sm[lane] : 0.f;
        #pragma unroll
        for (int off = 4; off > 0; off >>= 1)
            v += __shfl_xor_sync(0xffffffffu, v, off);
        if (lane == 0) out[b] = v + b2[0];
    }
}

// =====================================================================
extern "C" void kernel_launch(void* const* d_in, const int* in_sizes, int n_in,
                              void* d_out, int out_size)
{
    (void)in_sizes; (void)n_in; (void)out_size;
    const float* x1 = (const float*)d_in[0];
    const float* x2 = (const float*)d_in[1];
    const float* Wc = (const float*)d_in[2];
    const float* bc = (const float*)d_in[3];
    const float* W1 = (const float*)d_in[4];
    const float* b1 = (const float*)d_in[5];
    const float* W2 = (const float*)d_in[6];
    const float* b2 = (const float*)d_in[7];
    float* out = (float*)d_out;

    static bool attr_done = false;
    if (!attr_done) {
        cudaFuncSetAttribute(encode_kernel,
                             cudaFuncAttributeMaxDynamicSharedMemorySize, SMEM_BYTES);
        cudaFuncSetAttribute(fc1_kernel,
                             cudaFuncAttributeMaxDynamicSharedMemorySize, SMEM_BYTES);
        attr_done = true;
    }

    // one-time-per-launch tf32 weight images (~10us total)
    cvt_wc_kernel<<<(CC * WCP + 255) / 256, 256>>>(Wc);
    cvt_w1_kernel<<<((HH * 2 * CC) / 4 + 255) / 256, 256>>>(W1);

    dim3 g1(CC / 128, (BB * LL) / 256, 2);        // 4 x 512 x 2 = 4096 CTAs
    encode_kernel<<<g1, 256, SMEM_BYTES>>>(x1, x2, bc);

    dim3 g2(HH / 128, BB / 256);                  // 16 x 8 = 128 CTAs
    fc1_kernel<<<g2, 256, SMEM_BYTES>>>(b1);

    fc2_kernel<<<BB, 256>>>(W2, b2, out);
}

// round 15
// speedup vs baseline: 1.5885x; 1.5885x over previous
#include <cuda_runtime.h>
#include <cuda_fp16.h>
#include <cstdint>

// ---------------- problem constants ----------------
#define BB   2048      // batch
#define LL   64        // words / sentence
#define DD   300       // embedding dim (K of encoder GEMM)
#define CC   512       // conv out channels
#define HH   2048      // fc hidden
// encoder GEMM: M = BB*LL = 131072, N = CC = 512, K = 300 (padded 320)
// fc1 GEMM:     M = BB = 2048,     N = HH = 2048, K = 2*CC = 1024

#define WC2  160       // Wc half-image row stride in half2 (320 halfs, zero-padded)
#define W12  512       // W1 half-image row stride in half2 (1024 halfs)

// ---------------- scratch (no allocations allowed) ----------------
__device__ float    g_e[2 * BB * CC];            // e1 | e2   (8 MB)
__device__ float    g_h[(size_t)BB * HH];        // tanh hidden (16 MB)
__device__ uint32_t g_wh[CC * WC2];              // half image of Wc (0.3 MB)
__device__ uint32_t g_w1h[(size_t)HH * W12];     // half image of W1 (4 MB)

// ---------------- helpers ----------------
__device__ __forceinline__ uint32_t pk2(float a, float b) {
    __half2 h = __floats2half2_rn(a, b);     // memory order [h(a), h(b)]
    return *(uint32_t*)&h;
}

__device__ __forceinline__ void mma_f16(float c[4], const uint32_t a[4], const uint32_t b[2]) {
    asm volatile(
        "mma.sync.aligned.m16n8k16.row.col.f32.f16.f16.f32 "
        "{%0,%1,%2,%3}, {%4,%5,%6,%7}, {%8,%9}, {%0,%1,%2,%3};"
        : "+f"(c[0]), "+f"(c[1]), "+f"(c[2]), "+f"(c[3])
        : "r"(a[0]), "r"(a[1]), "r"(a[2]), "r"(a[3]), "r"(b[0]), "r"(b[1]));
}

__device__ __forceinline__ void cpa16(uint32_t dst, const void* src) {
    asm volatile("cp.async.cg.shared.global [%0], [%1], 16;"
                 :: "r"(dst), "l"(src));
}
__device__ __forceinline__ void cpa_commit() {
    asm volatile("cp.async.commit_group;");
}

// ---------------- tiling ----------------
// CTA tile: 256 (M) x 128 (N), K-tile 32 halfs (2 k16-steps), 8 warps of 64x64.
// smem unit: uint32 = half2.  Row stride 20 half2 (40 halfs) -> conflict-free
// fragment loads ({20g % 32} + tg hits all 32 banks).
#define SPW   20                       // smem row stride (half2 words)
#define ASW   (256 * SPW)              // half2 words per A stage
#define BSW   (128 * SPW)              // half2 words per B stage
#define SMEM_WORDS (2 * (ASW + BSW))
#define SMEM_BYTES (SMEM_WORDS * 4)    // 61440

// ---------------- per-warp compute on one staged K-tile ----------------
// NSTEP k16-steps; fragment/acc layout identical to the tf32 m16n8k8 kernel.
template <int NSTEP>
__device__ __forceinline__ void compute_tile(const uint32_t* __restrict__ As,
                                             const uint32_t* __restrict__ Bs,
                                             int wm, int wn, int g, int tg,
                                             float acc[4][8][4])
{
    #pragma unroll
    for (int s = 0; s < NSTEP; s++) {
        const int kk = s * 8;          // half2 offset of this k16-step
        uint32_t a[4][4], b[8][2];
        #pragma unroll
        for (int f = 0; f < 4; f++) {
            int r = wm * 64 + f * 16;
            a[f][0] = As[(r + g    ) * SPW + kk + tg    ];
            a[f][1] = As[(r + g + 8) * SPW + kk + tg    ];
            a[f][2] = As[(r + g    ) * SPW + kk + tg + 4];
            a[f][3] = As[(r + g + 8) * SPW + kk + tg + 4];
        }
        #pragma unroll
        for (int ni = 0; ni < 8; ni++) {
            int c = wn * 64 + ni * 8;
            b[ni][0] = Bs[(c + g) * SPW + kk + tg    ];
            b[ni][1] = Bs[(c + g) * SPW + kk + tg + 4];
        }
        #pragma unroll
        for (int f = 0; f < 4; f++)
            #pragma unroll
            for (int ni = 0; ni < 8; ni++)
                mma_f16(acc[f][ni], a[f], b[ni]);
    }
}

// =====================================================================
// Kernel 0a/0b: one-time half images of the weights
// =====================================================================
__global__ __launch_bounds__(256)
void cvt_wc_kernel(const float* __restrict__ Wc)
{
    int idx = blockIdx.x * 256 + threadIdx.x;
    if (idx >= CC * WC2) return;
    int row = idx / WC2, c2 = idx % WC2;
    int k0 = c2 * 2, k1 = k0 + 1;
    float f0 = (k0 < DD) ? Wc[(size_t)row * DD + k0] : 0.f;
    float f1 = (k1 < DD) ? Wc[(size_t)row * DD + k1] : 0.f;
    g_wh[idx] = pk2(f0, f1);
}

__global__ __launch_bounds__(256)
void cvt_w1_kernel(const float* __restrict__ W1)
{
    size_t idx = (size_t)blockIdx.x * 256 + threadIdx.x;  // half2 index
    float2 v = *(const float2*)(W1 + idx * 2);
    g_w1h[idx] = pk2(v.x, v.y);
}

// =====================================================================
// Kernel 1: encoder.  grid = (C/128, (B*L)/256, 2), block = 256
// relu(max_L(x @ Wc^T) + bc) folded into epilogue; warp m-strip = 1 sentence.
// A: LDG x fp32 -> regs -> cvt@STS (double-buffered).  B: cp.async raw g_wh.
// =====================================================================
__global__ __launch_bounds__(256, 1)
void encode_kernel(const float* __restrict__ x1, const float* __restrict__ x2,
                   const float* __restrict__ bc)
{
    extern __shared__ uint32_t sh[];
    uint32_t sbase = (uint32_t)__cvta_generic_to_shared(sh);

    const float* __restrict__ x = (blockIdx.z == 0) ? x1 : x2;
    const int mbase = blockIdx.y * 256;
    const int nbase = blockIdx.x * 128;

    const int tid  = threadIdx.x;
    const int warp = tid >> 5, lane = tid & 31;
    const int wm = warp >> 1;      // 4 m-strips of 64 rows (one sentence each)
    const int wn = warp & 1;       // 2 n-strips of 64 cols
    const int g  = lane >> 2, tg = lane & 3;

    const int arow = tid >> 3;          // A loader: +it*32, 8 float4 chunks/row
    const int afch = (tid & 7) * 4;     // float (=half) offset within the 32-K tile
    const int brow = tid >> 2;          // B loader: +it*64, 4 16B chunks/row
    const int bch  = (tid & 3) * 4;     // half2 offset (4 half2 = 16B)

    float4 ra[8];

    auto ldgA = [&](int kb) {           // kb in halfs (== floats of x)
        const int k = kb + afch;
        #pragma unroll
        for (int it = 0; it < 8; it++) {
            int row = arow + it * 32;
            ra[it] = (k < DD)
                ? *(const float4*)(x + (size_t)(mbase + row) * DD + k)
                : make_float4(0.f, 0.f, 0.f, 0.f);
        }
    };
    auto stsA = [&](int buf) {
        #pragma unroll
        for (int it = 0; it < 8; it++) {
            int row = arow + it * 32;
            uint32_t* d = sh + buf * ASW + row * SPW + (afch >> 1);
            d[0] = pk2(ra[it].x, ra[it].y);
            d[1] = pk2(ra[it].z, ra[it].w);
        }
    };
    auto cpB = [&](int buf, int kb2) {  // kb2 in half2 (16 per K-tile)
        #pragma unroll
        for (int it = 0; it < 2; it++) {
            int row = brow + it * 64;
            const uint32_t* src = g_wh + (size_t)(nbase + row) * WC2 + kb2 + bch;
            uint32_t dst = sbase + (uint32_t)(2 * ASW + buf * BSW + row * SPW + bch) * 4u;
            cpa16(dst, src);            // image is zero-padded to 320 halfs
        }
    };

    float acc[4][8][4] = {};

    const int NK = 10;     // K tiles of 32 halfs (300 -> 320 padded; tail trimmed)
    // prologue
    cpB(0, 0);
    cpa_commit();
    ldgA(0);
    stsA(0);
    asm volatile("cp.async.wait_group 0;");
    __syncthreads();

    #pragma unroll 1
    for (int i = 0; i < NK; i++) {
        if (i + 1 < NK) {
            cpB((i + 1) & 1, (i + 1) * 16);
            cpa_commit();
            ldgA((i + 1) * 32);
        }

        const uint32_t* As = sh + (i & 1) * ASW;
        const uint32_t* Bs = sh + 2 * ASW + (i & 1) * BSW;
        if (i == NK - 1)   // one k16-step: k = 288..303 covers the 300 real cols
            compute_tile<1>(As, Bs, wm, wn, g, tg, acc);
        else
            compute_tile<2>(As, Bs, wm, wn, g, tg, acc);

        if (i + 1 < NK) {
            stsA((i + 1) & 1);
            asm volatile("cp.async.wait_group 0;");
            __syncthreads();
        }
    }

    // ---- epilogue: max over the warp's 64 rows (== one sentence) ----
    // relu(max + bc) == max(relu(.+bc)) since bias is per-column.
    const size_t sent = (size_t)blockIdx.y * 4 + wm;       // global sentence
    float* __restrict__ eout = g_e + ((size_t)blockIdx.z * BB + sent) * CC + nbase;

    #pragma unroll
    for (int ni = 0; ni < 8; ni++) {
        #pragma unroll
        for (int j = 0; j < 2; j++) {
            float m = -3.4e38f;
            #pragma unroll
            for (int f = 0; f < 4; f++)
                m = fmaxf(m, fmaxf(acc[f][ni][j], acc[f][ni][j + 2]));
            #pragma unroll
            for (int off = 4; off < 32; off <<= 1)
                m = fmaxf(m, __shfl_xor_sync(0xffffffffu, m, off));
            if (g == 0) {
                int col = wn * 64 + ni * 8 + 2 * tg + j;
                eout[col] = fmaxf(m + bc[nbase + col], 0.f);
            }
        }
    }
}

// =====================================================================
// Kernel 2: FC1.  grid = (H/128, B/256), block = 256
// feat = [e1-e2 | e1*e2] computed on the fly (fp32 A-side, cvt at STS).
// B: cp.async raw of g_w1h.  h = tanh(feat @ W1^T + b1)
// =====================================================================
__global__ __launch_bounds__(256, 1)
void fc1_kernel(const float* __restrict__ b1)
{
    extern __shared__ uint32_t sh[];
    uint32_t sbase = (uint32_t)__cvta_generic_to_shared(sh);

    const int mbase = blockIdx.y * 256;
    const int nbase = blockIdx.x * 128;

    const int tid  = threadIdx.x;
    const int warp = tid >> 5, lane = tid & 31;
    const int wm = warp >> 1, wn = warp & 1;
    const int g  = lane >> 2, tg = lane & 3;

    const float* __restrict__ e1 = g_e;
    const float* __restrict__ e2 = g_e + (size_t)BB * CC;

    const int arow = tid >> 3;
    const int afch = (tid & 7) * 4;
    const int brow = tid >> 2;
    const int bch  = (tid & 3) * 4;

    float acc[4][8][4] = {};
    float4 ra[8];

    auto ldgA = [&](int kb) {
        const int j = kb + afch;
        #pragma unroll
        for (int it = 0; it < 8; it++) {
            int r = mbase + arow + it * 32;
            if (j < CC) {
                float4 p = *(const float4*)(e1 + (size_t)r * CC + j);
                float4 q = *(const float4*)(e2 + (size_t)r * CC + j);
                ra[it] = make_float4(p.x - q.x, p.y - q.y, p.z - q.z, p.w - q.w);
            } else {
                int j2 = j - CC;
                float4 p = *(const float4*)(e1 + (size_t)r * CC + j2);
                float4 q = *(const float4*)(e2 + (size_t)r * CC + j2);
                ra[it] = make_float4(p.x * q.x, p.y * q.y, p.z * q.z, p.w * q.w);
            }
        }
    };
    auto stsA = [&](int buf) {
        #pragma unroll
        for (int it = 0; it < 8; it++) {
            int row = arow + it * 32;
            uint32_t* d = sh + buf * ASW + row * SPW + (afch >> 1);
            d[0] = pk2(ra[it].x, ra[it].y);
            d[1] = pk2(ra[it].z, ra[it].w);
        }
    };
    auto cpB = [&](int buf, int kb2) {
        #pragma unroll
        for (int it = 0; it < 2; it++) {
            int row = brow + it * 64;
            const uint32_t* src = g_w1h + (size_t)(nbase + row) * W12 + kb2 + bch;
            uint32_t dst = sbase + (uint32_t)(2 * ASW + buf * BSW + row * SPW + bch) * 4u;
            cpa16(dst, src);
        }
    };

    const int NK = (2 * CC) / 32;   // 32 K-tiles of 32 halfs
    // prologue
    cpB(0, 0);
    cpa_commit();
    ldgA(0);
    stsA(0);
    asm volatile("cp.async.wait_group 0;");
    __syncthreads();

    #pragma unroll 1
    for (int i = 0; i < NK; i++) {
        if (i + 1 < NK) {
            cpB((i + 1) & 1, (i + 1) * 16);
            cpa_commit();
            ldgA((i + 1) * 32);
        }

        const uint32_t* As = sh + (i & 1) * ASW;
        const uint32_t* Bs = sh + 2 * ASW + (i & 1) * BSW;
        compute_tile<2>(As, Bs, wm, wn, g, tg, acc);

        if (i + 1 < NK) {
            stsA((i + 1) & 1);
            asm volatile("cp.async.wait_group 0;");
            __syncthreads();
        }
    }

    // epilogue: bias + tanh, direct store
    #pragma unroll
    for (int f = 0; f < 4; f++) {
        #pragma unroll
        for (int ni = 0; ni < 8; ni++) {
            #pragma unroll
            for (int q = 0; q < 4; q++) {
                int row = mbase + wm * 64 + f * 16 + g + ((q >> 1) ? 8 : 0);
                int col = nbase + wn * 64 + ni * 8 + 2 * tg + (q & 1);
                g_h[(size_t)row * HH + col] = tanhf(acc[f][ni][q] + b1[col]);
            }
        }
    }
}

// =====================================================================
// Kernel 3: FC2 (H -> 1), fp32, float4 loads.  grid = B, block = 256
// =====================================================================
__global__ __launch_bounds__(256)
void fc2_kernel(const float* __restrict__ W2, const float* __restrict__ b2,
                float* __restrict__ out)
{
    const int b = blockIdx.x;
    const float4* __restrict__ h4 = (const float4*)(g_h + (size_t)b * HH);
    const float4* __restrict__ w4 = (const float4*)W2;
    float s = 0.f;
    #pragma unroll
    for (int i = 0; i < 2; i++) {
        int idx = threadIdx.x + i * 256;
        float4 hv = h4[idx], wv = w4[idx];
        s += hv.x * wv.x + hv.y * wv.y + hv.z * wv.z + hv.w * wv.w;
    }
    #pragma unroll
    for (int off = 16; off > 0; off >>= 1)
        s += __shfl_xor_sync(0xffffffffu, s, off);
    __shared__ float sm[8];
    int warp = threadIdx.x >> 5, lane = threadIdx.x & 31;
    if (lane == 0) sm[warp] = s;
    __syncthreads();
    if (warp == 0) {
        float v = (lane < 8) ? sm[lane] : 0.f;
        #pragma unroll
        for (int off = 4; off > 0; off >>= 1)
            v += __shfl_xor_sync(0xffffffffu, v, off);
        if (lane == 0) out[b] = v + b2[0];
    }
}

// =====================================================================
extern "C" void kernel_launch(void* const* d_in, const int* in_sizes, int n_in,
                              void* d_out, int out_size)
{
    (void)in_sizes; (void)n_in; (void)out_size;
    const float* x1 = (const float*)d_in[0];
    const float* x2 = (const float*)d_in[1];
    const float* Wc = (const float*)d_in[2];
    const float* bc = (const float*)d_in[3];
    const float* W1 = (const float*)d_in[4];
    const float* b1 = (const float*)d_in[5];
    const float* W2 = (const float*)d_in[6];
    const float* b2 = (const float*)d_in[7];
    float* out = (float*)d_out;

    static bool attr_done = false;
    if (!attr_done) {
        cudaFuncSetAttribute(encode_kernel,
                             cudaFuncAttributeMaxDynamicSharedMemorySize, SMEM_BYTES);
        cudaFuncSetAttribute(fc1_kernel,
                             cudaFuncAttributeMaxDynamicSharedMemorySize, SMEM_BYTES);
        attr_done = true;
    }

    // one-time-per-launch half weight images (~8us total)
    cvt_wc_kernel<<<(CC * WC2 + 255) / 256, 256>>>(Wc);
    cvt_w1_kernel<<<((HH * W12) + 255) / 256, 256>>>(W1);

    dim3 g1(CC / 128, (BB * LL) / 256, 2);        // 4 x 512 x 2 = 4096 CTAs
    encode_kernel<<<g1, 256, SMEM_BYTES>>>(x1, x2, bc);

    dim3 g2(HH / 128, BB / 256);                  // 16 x 8 = 128 CTAs
    fc1_kernel<<<g2, 256, SMEM_BYTES>>>(b1);

    fc2_kernel<<<BB, 256>>>(W2, b2, out);
}